// round 1
// baseline (speedup 1.0000x reference)
#include <cuda_runtime.h>
#include <cuda_bf16.h>
#include <cstdint>
#include <math.h>

// Problem constants
#define BB 2
#define LL 4096
#define HH 2048
#define LK 128
#define KDIM HH          // GEMM K = H = 2048
#define NHALF HH         // GLU half width = 2048

// Scratch (static __device__ arrays: allocation-free per harness rules)
__device__ float g_buf[(size_t)BB * LL * HH];     // gelu(conv) output, TF32-rounded bits, [M=B*L, K=H]
__device__ float w_tf[(size_t)2 * HH * HH];       // W rounded to TF32, [4096, 2048]

__device__ __forceinline__ float to_tf32(float x) {
    float r;
    asm("cvt.rna.tf32.f32 %0, %1;" : "=f"(r) : "f"(x));
    return r;
}

__device__ __forceinline__ void cp_async16(void* smem_ptr, const void* gptr) {
    uint32_t s = (uint32_t)__cvta_generic_to_shared(smem_ptr);
    asm volatile("cp.async.cg.shared.global [%0], [%1], 16;\n" :: "r"(s), "l"(gptr));
}
__device__ __forceinline__ void cp_commit() { asm volatile("cp.async.commit_group;\n"); }
template <int N>
__device__ __forceinline__ void cp_wait() { asm volatile("cp.async.wait_group %0;\n" :: "n"(N)); }

// ---------------------------------------------------------------------------
// Kernel 0: round W to TF32 once (producer-side cvt so GEMM inner loop has none)
// ---------------------------------------------------------------------------
__global__ void wconv_kernel(const float* __restrict__ W) {
    size_t i = ((size_t)blockIdx.x * 256 + threadIdx.x) * 4;
    float4 v = *(const float4*)(W + i);
    v.x = to_tf32(v.x); v.y = to_tf32(v.y); v.z = to_tf32(v.z); v.w = to_tf32(v.w);
    *(float4*)(w_tf + i) = v;
}

// ---------------------------------------------------------------------------
// Kernel 1: causal long-conv (Lk=128) + 2*D*u skip + exact GELU -> g_buf (TF32)
// Tile: 64 l x 32 h per block, 256 threads, 8 outputs/thread, register-windowed
// taps (23 LDS per 64 FMA).
// ---------------------------------------------------------------------------
__global__ __launch_bounds__(256) void conv_gelu_kernel(
    const float* __restrict__ u, const float* __restrict__ kern,
    const float* __restrict__ D)
{
    __shared__ float ks[LK][32];        // squashed kernel, transposed [j][h]
    __shared__ float us[64 + LK - 1][32]; // u window [t][h], t=0 -> l0-127

    const int b  = blockIdx.z;
    const int l0 = blockIdx.x * 64;
    const int h0 = blockIdx.y * 32;
    const int tid = threadIdx.x;

    // Load + squash kernel taps (coalesced global, conflicted smem store is fine)
    for (int idx = tid; idx < LK * 32; idx += 256) {
        int hh = idx >> 7, j = idx & 127;
        float v = kern[(h0 + hh) * LK + j];
        float a = fabsf(v) - 0.003f;
        ks[j][hh] = (a > 0.f) ? copysignf(a, v) : 0.f;
    }
    // Load u window (zero-pad l<0)
    const float* ub = u + (size_t)b * LL * HH;
    for (int idx = tid; idx < 191 * 32; idx += 256) {
        int t = idx >> 5, hh = idx & 31;
        int gl = l0 - (LK - 1) + t;
        us[t][hh] = (gl >= 0) ? ub[(size_t)gl * HH + h0 + hh] : 0.f;
    }
    __syncthreads();

    const int tx = tid & 31;            // h lane
    const int ty = tid >> 5;            // l group (0..7)
    const int lyb = ty * 8;

    float acc[8];
#pragma unroll
    for (int i = 0; i < 8; i++) acc[i] = 0.f;

    for (int j = 0; j < LK; j += 8) {
        float kr[8];
#pragma unroll
        for (int jj = 0; jj < 8; jj++) kr[jj] = ks[j + jj][tx];
        float w[15];
        const int tb = 120 + lyb - j;   // t index for s=0
#pragma unroll
        for (int s = 0; s < 15; s++) w[s] = us[tb + s][tx];
#pragma unroll
        for (int jj = 0; jj < 8; jj++)
#pragma unroll
            for (int i = 0; i < 8; i++)
                acc[i] = fmaf(kr[jj], w[7 - jj + i], acc[i]);
    }

    const float Dv = 2.f * D[h0 + tx];
#pragma unroll
    for (int i = 0; i < 8; i++) {
        int ly = lyb + i;
        float uv = us[(LK - 1) + ly][tx];
        float y = acc[i] + Dv * uv;
        float g = y * normcdff(y);      // exact-erf GELU
        g_buf[((size_t)b * LL + l0 + ly) * HH + h0 + tx] = to_tf32(g);
    }
}

// ---------------------------------------------------------------------------
// Kernel 2: fused GEMM + GLU via TF32 mma.sync.m16n8k8
//   z = g @ W^T + bias ; out = z[:, :2048] * sigmoid(z[:, 2048:])
// Block tile: 128(M) x 128(B-tile rows) x 16(K). B tile rows interleave
// a-half / gate-half of W (row 2q -> W[NH+q], row 2q+1 -> W[2048+NH+q]) so the
// accumulator column pair (c0,c1) is exactly one (a, gate) pair per thread.
// Warps: 4(M) x 2(N); 256 threads; double-buffered cp.async.
// ---------------------------------------------------------------------------
__global__ __launch_bounds__(256) void gemm_glu_kernel(
    const float* __restrict__ bias, float* __restrict__ out)
{
    __shared__ float As[2][128][20];    // pad 20 -> conflict-free fragment LDS
    __shared__ float Bs[2][128][20];

    const int tid  = threadIdx.x;
    const int lane = tid & 31;
    const int wid  = tid >> 5;
    const int warpM = wid & 3;          // 0..3 -> 32 rows each
    const int warpN = wid >> 2;         // 0..1 -> 64 B-tile rows each
    const int m0 = blockIdx.y * 128;
    const int NH = blockIdx.x * 64;     // output pair-column origin

    const int lr = tid >> 2;            // 0..63
    const int lc = (tid & 3) * 4;       // float4 column

    auto load_stage = [&](int s, int k0) {
#pragma unroll
        for (int rr = 0; rr < 2; rr++) {
            int row = lr + rr * 64;
            cp_async16(&As[s][row][lc], g_buf + (size_t)(m0 + row) * KDIM + k0 + lc);
            int q = row >> 1;
            int wrow = (row & 1) ? (NHALF + NH + q) : (NH + q);
            cp_async16(&Bs[s][row][lc], w_tf + (size_t)wrow * KDIM + k0 + lc);
        }
    };

    float acc[2][8][4];
#pragma unroll
    for (int mt = 0; mt < 2; mt++)
#pragma unroll
        for (int nt = 0; nt < 8; nt++)
#pragma unroll
            for (int c = 0; c < 4; c++) acc[mt][nt][c] = 0.f;

    load_stage(0, 0);
    cp_commit();
    cp_wait<0>();
    __syncthreads();

    const int NK = KDIM / 16;           // 128
    for (int kt = 0; kt < NK; kt++) {
        int cur = kt & 1;
        if (kt + 1 < NK) { load_stage(cur ^ 1, (kt + 1) * 16); cp_commit(); }

#pragma unroll
        for (int k8 = 0; k8 < 2; k8++) {
            const int kk = k8 * 8;
            uint32_t a[2][4], bf[8][2];
#pragma unroll
            for (int mt = 0; mt < 2; mt++) {
                int row = warpM * 32 + mt * 16 + (lane >> 2);
                int col = kk + (lane & 3);
                a[mt][0] = __float_as_uint(As[cur][row][col]);
                a[mt][1] = __float_as_uint(As[cur][row + 8][col]);
                a[mt][2] = __float_as_uint(As[cur][row][col + 4]);
                a[mt][3] = __float_as_uint(As[cur][row + 8][col + 4]);
            }
#pragma unroll
            for (int nt = 0; nt < 8; nt++) {
                int brow = warpN * 64 + nt * 8 + (lane >> 2);
                bf[nt][0] = __float_as_uint(Bs[cur][brow][kk + (lane & 3)]);
                bf[nt][1] = __float_as_uint(Bs[cur][brow][kk + 4 + (lane & 3)]);
            }
#pragma unroll
            for (int mt = 0; mt < 2; mt++)
#pragma unroll
                for (int nt = 0; nt < 8; nt++) {
                    asm volatile(
                        "mma.sync.aligned.m16n8k8.row.col.f32.tf32.tf32.f32 "
                        "{%0,%1,%2,%3}, {%4,%5,%6,%7}, {%8,%9}, {%0,%1,%2,%3};\n"
                        : "+f"(acc[mt][nt][0]), "+f"(acc[mt][nt][1]),
                          "+f"(acc[mt][nt][2]), "+f"(acc[mt][nt][3])
                        : "r"(a[mt][0]), "r"(a[mt][1]), "r"(a[mt][2]), "r"(a[mt][3]),
                          "r"(bf[nt][0]), "r"(bf[nt][1]));
                }
        }

        if (kt + 1 < NK) cp_wait<0>();
        __syncthreads();
    }

    // Epilogue: bias + GLU, write out[m, NH + pair]
#pragma unroll
    for (int mt = 0; mt < 2; mt++) {
        int row = m0 + warpM * 32 + mt * 16 + (lane >> 2);
#pragma unroll
        for (int nt = 0; nt < 8; nt++) {
            int p = warpN * 32 + nt * 4 + (lane & 3);   // pair index within block
            int colA = NH + p;
            float ba = bias[colA];
            float bg = bias[NHALF + colA];

            float za0 = acc[mt][nt][0] + ba;
            float zg0 = acc[mt][nt][1] + bg;
            out[(size_t)row * NHALF + colA] = za0 * (1.f / (1.f + expf(-zg0)));

            float za1 = acc[mt][nt][2] + ba;
            float zg1 = acc[mt][nt][3] + bg;
            out[(size_t)(row + 8) * NHALF + colA] = za1 * (1.f / (1.f + expf(-zg1)));
        }
    }
}

// ---------------------------------------------------------------------------
extern "C" void kernel_launch(void* const* d_in, const int* in_sizes, int n_in,
                              void* d_out, int out_size)
{
    const float* u    = (const float*)d_in[0];  // [2,4096,2048]
    const float* kern = (const float*)d_in[1];  // [1,2048,128]
    const float* D    = (const float*)d_in[2];  // [1,2048]
    const float* W    = (const float*)d_in[3];  // [4096,2048]
    const float* bias = (const float*)d_in[4];  // [4096]
    float* out = (float*)d_out;                 // [2,4096,2048]

    // W -> TF32 (8388608 elems / (256 threads * 4) = 8192 blocks)
    wconv_kernel<<<8192, 256>>>(W);

    // conv + skip + gelu: grid (L/64, H/32, B)
    conv_gelu_kernel<<<dim3(LL / 64, HH / 32, BB), 256>>>(u, kern, D);

    // fused GEMM+GLU: grid (2048/64 pair-cols, 8192/128 rows)
    gemm_glu_kernel<<<dim3(NHALF / 64, (BB * LL) / 128), 256>>>(bias, out);
}

// round 4
// speedup vs baseline: 2.0987x; 2.0987x over previous
#include <cuda_runtime.h>
#include <cuda_fp16.h>
#include <cstdint>
#include <math.h>

// Problem constants
#define BB 2
#define LL 4096
#define HH 2048
#define LK 128
#define KDIM HH          // GEMM K = H = 2048
#define NHALF HH         // GLU half width = 2048

// Scratch (static __device__ arrays: allocation-free per harness rules)
__device__ __half g_buf[(size_t)BB * LL * HH];   // gelu(conv) output fp16, [M=B*L, K=H]
__device__ __half w_h[(size_t)2 * HH * HH];      // W fp16, [4096, 2048]

__device__ __forceinline__ void cp_async16(void* smem_ptr, const void* gptr) {
    uint32_t s = (uint32_t)__cvta_generic_to_shared(smem_ptr);
    asm volatile("cp.async.cg.shared.global [%0], [%1], 16;\n" :: "r"(s), "l"(gptr));
}
__device__ __forceinline__ void cp_commit() { asm volatile("cp.async.commit_group;\n"); }
template <int N>
__device__ __forceinline__ void cp_wait() { asm volatile("cp.async.wait_group %0;\n" :: "n"(N)); }

__device__ __forceinline__ void ldsm_x4(uint32_t& r0, uint32_t& r1, uint32_t& r2, uint32_t& r3,
                                        uint32_t addr) {
    asm volatile("ldmatrix.sync.aligned.m8n8.x4.shared.b16 {%0,%1,%2,%3}, [%4];"
                 : "=r"(r0), "=r"(r1), "=r"(r2), "=r"(r3) : "r"(addr));
}

__device__ __forceinline__ void mma_f16(float* c, const uint32_t* a, const uint32_t* b) {
    asm volatile(
        "mma.sync.aligned.m16n8k16.row.col.f32.f16.f16.f32 "
        "{%0,%1,%2,%3}, {%4,%5,%6,%7}, {%8,%9}, {%0,%1,%2,%3};\n"
        : "+f"(c[0]), "+f"(c[1]), "+f"(c[2]), "+f"(c[3])
        : "r"(a[0]), "r"(a[1]), "r"(a[2]), "r"(a[3]), "r"(b[0]), "r"(b[1]));
}

__device__ __forceinline__ uint32_t h2_bits(__half2 h) {
    union { __half2 h; uint32_t u; } cvt;
    cvt.h = h;
    return cvt.u;
}

// ---------------------------------------------------------------------------
// Kernel 0: W -> fp16
// ---------------------------------------------------------------------------
__global__ void wconv_kernel(const float* __restrict__ W) {
    size_t i = ((size_t)blockIdx.x * 256 + threadIdx.x) * 4;
    float4 v = *(const float4*)(W + i);
    uint2 o;
    o.x = h2_bits(__floats2half2_rn(v.x, v.y));
    o.y = h2_bits(__floats2half2_rn(v.z, v.w));
    *(uint2*)(w_h + i) = o;
}

// ---------------------------------------------------------------------------
// Kernel 1: causal long-conv (Lk=128) + 2*D*u skip + exact GELU -> g_buf fp16
// ---------------------------------------------------------------------------
__global__ __launch_bounds__(256) void conv_gelu_kernel(
    const float* __restrict__ u, const float* __restrict__ kern,
    const float* __restrict__ D)
{
    __shared__ float ks[LK][32];
    __shared__ float us[64 + LK - 1][32];

    const int b  = blockIdx.z;
    const int l0 = blockIdx.x * 64;
    const int h0 = blockIdx.y * 32;
    const int tid = threadIdx.x;

    for (int idx = tid; idx < LK * 32; idx += 256) {
        int hh = idx >> 7, j = idx & 127;
        float v = kern[(h0 + hh) * LK + j];
        float a = fabsf(v) - 0.003f;
        ks[j][hh] = (a > 0.f) ? copysignf(a, v) : 0.f;
    }
    const float* ub = u + (size_t)b * LL * HH;
    for (int idx = tid; idx < 191 * 32; idx += 256) {
        int t = idx >> 5, hh = idx & 31;
        int gl = l0 - (LK - 1) + t;
        us[t][hh] = (gl >= 0) ? ub[(size_t)gl * HH + h0 + hh] : 0.f;
    }
    __syncthreads();

    const int tx = tid & 31;
    const int ty = tid >> 5;
    const int lyb = ty * 8;

    float acc[8];
#pragma unroll
    for (int i = 0; i < 8; i++) acc[i] = 0.f;

    for (int j = 0; j < LK; j += 8) {
        float kr[8];
#pragma unroll
        for (int jj = 0; jj < 8; jj++) kr[jj] = ks[j + jj][tx];
        float w[15];
        const int tb = 120 + lyb - j;
#pragma unroll
        for (int s = 0; s < 15; s++) w[s] = us[tb + s][tx];
#pragma unroll
        for (int jj = 0; jj < 8; jj++)
#pragma unroll
            for (int i = 0; i < 8; i++)
                acc[i] = fmaf(kr[jj], w[7 - jj + i], acc[i]);
    }

    const float Dv = 2.f * D[h0 + tx];
#pragma unroll
    for (int i = 0; i < 8; i++) {
        int ly = lyb + i;
        float uv = us[(LK - 1) + ly][tx];
        float y = acc[i] + Dv * uv;
        float g = y * normcdff(y);
        g_buf[((size_t)b * LL + l0 + ly) * HH + h0 + tx] = __float2half_rn(g);
    }
}

// ---------------------------------------------------------------------------
// Kernel 2: FP16 mma.sync GEMM + fused GLU epilogue
//   CTA tile: M=128 x 128 B-rows (64 GLU pairs) x K=2048 (32 stages of 64)
//   B rows interleave a/gate halves of W: row 2q -> W[nb0+q], 2q+1 -> W[2048+nb0+q]
//   => accumulator cols (2c, 2c+1) = (a, gate) pair.
//   8 warps: 4(M) x 2(N). ldmatrix.x4 fragments, SW128 swizzle, 3-stage cp.async.
// ---------------------------------------------------------------------------
#define KST 64                       // k halves per stage (128 B/row)
#define STG_BYTES 16384              // 128 rows * 128 B
#define ST_A 0
#define ST_B (3 * STG_BYTES)
#define SMEM_TOTAL_G (6 * STG_BYTES) // 96 KB

__device__ __forceinline__ uint32_t sw128(uint32_t off) {
    return off ^ ((off >> 3) & 0x70);
}

__global__ __launch_bounds__(256) void gemm_glu_f16(
    const float* __restrict__ bias, float* __restrict__ out)
{
    extern __shared__ char smem[];
    const uint32_t sb = (uint32_t)__cvta_generic_to_shared(smem);
    const int tid  = threadIdx.x;
    const int lane = tid & 31;
    const int wid  = tid >> 5;
    const int warpM = wid & 3;               // 32 M-rows each
    const int warpN = wid >> 2;              // 64 B-rows each
    const int m0  = blockIdx.y * 128;
    const int nb0 = blockIdx.x * 64;         // output-pair-column base

    auto load_stage = [&](int slot, int k0) {
#pragma unroll
        for (int i = 0; i < 8; i++) {
            int idx = tid + i * 256;
            int row = (idx >> 3) & 127, ch = idx & 7;
            uint32_t sw = sw128(row * 128 + ch * 16);
            if (idx < 1024) {
                cp_async16(smem + ST_A + slot * STG_BYTES + sw,
                           g_buf + (size_t)(m0 + row) * KDIM + k0 + ch * 8);
            } else {
                int q = row >> 1;
                int wrow = (row & 1) ? (NHALF + nb0 + q) : (nb0 + q);
                cp_async16(smem + ST_B + slot * STG_BYTES + sw,
                           w_h + (size_t)wrow * KDIM + k0 + ch * 8);
            }
        }
        cp_commit();
    };

    float acc[2][8][4];
#pragma unroll
    for (int mt = 0; mt < 2; mt++)
#pragma unroll
        for (int nt = 0; nt < 8; nt++)
#pragma unroll
            for (int c = 0; c < 4; c++) acc[mt][nt][c] = 0.f;

    const int NST = KDIM / KST;              // 32
    load_stage(0, 0);
    load_stage(1, KST);
    load_stage(2, 2 * KST);

    // Precompute per-thread fragment smem offsets (within a stage)
    const uint32_t a_row = warpM * 32 + (lane & 15);
    const uint32_t a_kh8 = (lane >> 4) << 3;                 // 0 or 8
    const uint32_t b_row = warpN * 64 + (lane & 7) + ((lane >> 4) << 3);
    const uint32_t b_kh8 = lane & 8;                         // 0 or 8

    for (int s = 0; s < NST; s++) {
        const int slot = s - (s / 3) * 3;    // s % 3
        cp_wait<2>();
        __syncthreads();

        const uint32_t abase = sb + ST_A + slot * STG_BYTES;
        const uint32_t bbase = sb + ST_B + slot * STG_BYTES;

#pragma unroll
        for (int k16 = 0; k16 < 4; k16++) {
            const uint32_t kk = k16 * 16;
            uint32_t a[2][4], bf[8][2];
#pragma unroll
            for (int mt = 0; mt < 2; mt++)
                ldsm_x4(a[mt][0], a[mt][1], a[mt][2], a[mt][3],
                        abase + sw128((a_row + mt * 16) * 128 + (kk + a_kh8) * 2));
#pragma unroll
            for (int nt2 = 0; nt2 < 4; nt2++)
                ldsm_x4(bf[2 * nt2][0], bf[2 * nt2][1], bf[2 * nt2 + 1][0], bf[2 * nt2 + 1][1],
                        bbase + sw128((b_row + nt2 * 16) * 128 + (kk + b_kh8) * 2));
#pragma unroll
            for (int mt = 0; mt < 2; mt++)
#pragma unroll
                for (int nt = 0; nt < 8; nt++)
                    mma_f16(acc[mt][nt], a[mt], bf[nt]);
        }

        __syncthreads();
        if (s + 3 < NST) load_stage(slot, (s + 3) * KST);
    }

    // Epilogue: bias + GLU. acc cols (0,1)=(a,gate) for pair p, (2,3) row+8.
#pragma unroll
    for (int mt = 0; mt < 2; mt++) {
        int row = m0 + warpM * 32 + mt * 16 + (lane >> 2);
#pragma unroll
        for (int nt = 0; nt < 8; nt++) {
            int col = nb0 + warpN * 32 + nt * 4 + (lane & 3);
            float ba = __ldg(bias + col);
            float bg = __ldg(bias + NHALF + col);

            float za0 = acc[mt][nt][0] + ba;
            float zg0 = acc[mt][nt][1] + bg;
            out[(size_t)row * NHALF + col] = za0 * (1.f / (1.f + __expf(-zg0)));

            float za1 = acc[mt][nt][2] + ba;
            float zg1 = acc[mt][nt][3] + bg;
            out[(size_t)(row + 8) * NHALF + col] = za1 * (1.f / (1.f + __expf(-zg1)));
        }
    }
}

// ---------------------------------------------------------------------------
extern "C" void kernel_launch(void* const* d_in, const int* in_sizes, int n_in,
                              void* d_out, int out_size)
{
    const float* u    = (const float*)d_in[0];  // [2,4096,2048]
    const float* kern = (const float*)d_in[1];  // [1,2048,128]
    const float* D    = (const float*)d_in[2];  // [1,2048]
    const float* W    = (const float*)d_in[3];  // [4096,2048]
    const float* bias = (const float*)d_in[4];  // [4096]
    float* out = (float*)d_out;                 // [2,4096,2048]

    cudaFuncSetAttribute(gemm_glu_f16, cudaFuncAttributeMaxDynamicSharedMemorySize, SMEM_TOTAL_G);

    wconv_kernel<<<8192, 256>>>(W);
    conv_gelu_kernel<<<dim3(LL / 64, HH / 32, BB), 256>>>(u, kern, D);
    // 32 pair-col tiles (64 cols each) x 64 M-tiles (128 rows each)
    gemm_glu_f16<<<dim3(NHALF / 64, (BB * LL) / 128), 256, SMEM_TOTAL_G>>>(bias, out);
}

// round 5
// speedup vs baseline: 2.1133x; 1.0069x over previous
#include <cuda_runtime.h>
#include <cuda_fp16.h>
#include <cstdint>
#include <math.h>

// Problem constants
#define BB 2
#define LL 4096
#define HH 2048
#define LK 128
#define KDIM HH          // GEMM K = H = 2048
#define NHALF HH         // GLU half width = 2048

// Scratch (static __device__ arrays: allocation-free per harness rules)
__device__ __half g_buf[(size_t)BB * LL * HH];   // gelu(conv) output fp16, [M=B*L, K=H]
__device__ __half w_h[(size_t)2 * HH * HH];      // W fp16, [4096, 2048]

__device__ __forceinline__ void cp_async16(void* smem_ptr, const void* gptr) {
    uint32_t s = (uint32_t)__cvta_generic_to_shared(smem_ptr);
    asm volatile("cp.async.cg.shared.global [%0], [%1], 16;\n" :: "r"(s), "l"(gptr));
}
__device__ __forceinline__ void cp_commit() { asm volatile("cp.async.commit_group;\n"); }
template <int N>
__device__ __forceinline__ void cp_wait() { asm volatile("cp.async.wait_group %0;\n" :: "n"(N)); }

__device__ __forceinline__ void ldsm_x4(uint32_t& r0, uint32_t& r1, uint32_t& r2, uint32_t& r3,
                                        uint32_t addr) {
    asm volatile("ldmatrix.sync.aligned.m8n8.x4.shared.b16 {%0,%1,%2,%3}, [%4];"
                 : "=r"(r0), "=r"(r1), "=r"(r2), "=r"(r3) : "r"(addr));
}

__device__ __forceinline__ void mma_f16(float* c, const uint32_t* a, const uint32_t* b) {
    asm volatile(
        "mma.sync.aligned.m16n8k16.row.col.f32.f16.f16.f32 "
        "{%0,%1,%2,%3}, {%4,%5,%6,%7}, {%8,%9}, {%0,%1,%2,%3};\n"
        : "+f"(c[0]), "+f"(c[1]), "+f"(c[2]), "+f"(c[3])
        : "r"(a[0]), "r"(a[1]), "r"(a[2]), "r"(a[3]), "r"(b[0]), "r"(b[1]));
}

__device__ __forceinline__ uint32_t h2_bits(__half2 h) {
    union { __half2 h; uint32_t u; } cvt;
    cvt.h = h;
    return cvt.u;
}

// ---------------------------------------------------------------------------
// Kernel 0: W -> fp16
// ---------------------------------------------------------------------------
__global__ void wconv_kernel(const float* __restrict__ W) {
    size_t i = ((size_t)blockIdx.x * 256 + threadIdx.x) * 4;
    float4 v = *(const float4*)(W + i);
    uint2 o;
    o.x = h2_bits(__floats2half2_rn(v.x, v.y));
    o.y = h2_bits(__floats2half2_rn(v.z, v.w));
    *(uint2*)(w_h + i) = o;
}

// ---------------------------------------------------------------------------
// Kernel 1: causal long-conv (Lk=128) + 2*D*u skip + exact GELU -> g_buf fp16
// ---------------------------------------------------------------------------
__global__ __launch_bounds__(256) void conv_gelu_kernel(
    const float* __restrict__ u, const float* __restrict__ kern,
    const float* __restrict__ D)
{
    __shared__ float ks[LK][32];
    __shared__ float us[64 + LK - 1][32];

    const int b  = blockIdx.z;
    const int l0 = blockIdx.x * 64;
    const int h0 = blockIdx.y * 32;
    const int tid = threadIdx.x;

    for (int idx = tid; idx < LK * 32; idx += 256) {
        int hh = idx >> 7, j = idx & 127;
        float v = kern[(h0 + hh) * LK + j];
        float a = fabsf(v) - 0.003f;
        ks[j][hh] = (a > 0.f) ? copysignf(a, v) : 0.f;
    }
    const float* ub = u + (size_t)b * LL * HH;
    for (int idx = tid; idx < 191 * 32; idx += 256) {
        int t = idx >> 5, hh = idx & 31;
        int gl = l0 - (LK - 1) + t;
        us[t][hh] = (gl >= 0) ? ub[(size_t)gl * HH + h0 + hh] : 0.f;
    }
    __syncthreads();

    const int tx = tid & 31;
    const int ty = tid >> 5;
    const int lyb = ty * 8;

    float acc[8];
#pragma unroll
    for (int i = 0; i < 8; i++) acc[i] = 0.f;

    for (int j = 0; j < LK; j += 8) {
        float kr[8];
#pragma unroll
        for (int jj = 0; jj < 8; jj++) kr[jj] = ks[j + jj][tx];
        float w[15];
        const int tb = 120 + lyb - j;
#pragma unroll
        for (int s = 0; s < 15; s++) w[s] = us[tb + s][tx];
#pragma unroll
        for (int jj = 0; jj < 8; jj++)
#pragma unroll
            for (int i = 0; i < 8; i++)
                acc[i] = fmaf(kr[jj], w[7 - jj + i], acc[i]);
    }

    const float Dv = 2.f * D[h0 + tx];
#pragma unroll
    for (int i = 0; i < 8; i++) {
        int ly = lyb + i;
        float uv = us[(LK - 1) + ly][tx];
        float y = acc[i] + Dv * uv;
        float g = y * normcdff(y);
        g_buf[((size_t)b * LL + l0 + ly) * HH + h0 + tx] = __float2half_rn(g);
    }
}

// ---------------------------------------------------------------------------
// Kernel 2: FP16 mma.sync GEMM + fused GLU epilogue
//   CTA tile: M=128 x 128 B-rows (64 GLU pairs) x K=2048 (32 stages of 64)
//   B rows interleave a/gate halves of W => acc cols (2c,2c+1) = (a,gate).
//   8 warps: 4(M) x 2(N). ldmatrix.x4, SW128 swizzle.
//   3-slot / 2-in-flight cp.async ring, ONE __syncthreads per stage,
//   loads issued before compute (2-stage lookahead), 2 CTAs/SM.
// ---------------------------------------------------------------------------
#define KST 64                       // k elements per stage (128 B/row)
#define STG_BYTES 16384              // 128 rows * 128 B
#define ST_A 0
#define ST_B (3 * STG_BYTES)
#define SMEM_TOTAL_G (6 * STG_BYTES) // 96 KB

__device__ __forceinline__ uint32_t sw128(uint32_t off) {
    return off ^ ((off >> 3) & 0x70);
}

__global__ __launch_bounds__(256, 2) void gemm_glu_f16(
    const float* __restrict__ bias, float* __restrict__ out)
{
    extern __shared__ char smem[];
    const uint32_t sb = (uint32_t)__cvta_generic_to_shared(smem);
    const int tid  = threadIdx.x;
    const int lane = tid & 31;
    const int wid  = tid >> 5;
    const int warpM = wid & 3;               // 32 M-rows each
    const int warpN = wid >> 2;              // 64 B-rows each
    const int m0  = blockIdx.y * 128;
    const int nb0 = blockIdx.x * 64;         // output-pair-column base

    auto load_stage = [&](int slot, int k0) {
#pragma unroll
        for (int i = 0; i < 8; i++) {
            int idx = tid + i * 256;
            int row = (idx >> 3) & 127, ch = idx & 7;
            uint32_t sw = sw128(row * 128 + ch * 16);
            if (idx < 1024) {
                cp_async16(smem + ST_A + slot * STG_BYTES + sw,
                           g_buf + (size_t)(m0 + row) * KDIM + k0 + ch * 8);
            } else {
                int q = row >> 1;
                int wrow = (row & 1) ? (NHALF + nb0 + q) : (nb0 + q);
                cp_async16(smem + ST_B + slot * STG_BYTES + sw,
                           w_h + (size_t)wrow * KDIM + k0 + ch * 8);
            }
        }
        cp_commit();
    };

    float acc[2][8][4];
#pragma unroll
    for (int mt = 0; mt < 2; mt++)
#pragma unroll
        for (int nt = 0; nt < 8; nt++)
#pragma unroll
            for (int c = 0; c < 4; c++) acc[mt][nt][c] = 0.f;

    const int NST = KDIM / KST;              // 32
    load_stage(0, 0);
    load_stage(1, KST);

    // Per-thread fragment smem offsets (within a stage)
    const uint32_t a_row = warpM * 32 + (lane & 15);
    const uint32_t a_kh8 = (lane >> 4) << 3;                 // 0 or 8
    const uint32_t b_row = warpN * 64 + (lane & 7) + ((lane >> 4) << 3);
    const uint32_t b_kh8 = lane & 8;                         // 0 or 8

    int slot = 0;
    for (int s = 0; s < NST; s++) {
        cp_wait<1>();
        __syncthreads();

        // Prefetch stage s+2 into the slot consumed at stage s-1 (freed by the
        // barrier above) — keeps memory latency off the critical path.
        if (s + 2 < NST) {
            int ls = slot + 2; if (ls >= 3) ls -= 3;
            load_stage(ls, (s + 2) * KST);
        }

        const uint32_t abase = sb + ST_A + slot * STG_BYTES;
        const uint32_t bbase = sb + ST_B + slot * STG_BYTES;

#pragma unroll
        for (int k16 = 0; k16 < 4; k16++) {
            const uint32_t kk = k16 * 16;
            uint32_t a[2][4], bf[8][2];
#pragma unroll
            for (int mt = 0; mt < 2; mt++)
                ldsm_x4(a[mt][0], a[mt][1], a[mt][2], a[mt][3],
                        abase + sw128((a_row + mt * 16) * 128 + (kk + a_kh8) * 2));
#pragma unroll
            for (int nt2 = 0; nt2 < 4; nt2++)
                ldsm_x4(bf[2 * nt2][0], bf[2 * nt2][1], bf[2 * nt2 + 1][0], bf[2 * nt2 + 1][1],
                        bbase + sw128((b_row + nt2 * 16) * 128 + (kk + b_kh8) * 2));
#pragma unroll
            for (int mt = 0; mt < 2; mt++)
#pragma unroll
                for (int nt = 0; nt < 8; nt++)
                    mma_f16(acc[mt][nt], a[mt], bf[nt]);
        }

        if (++slot >= 3) slot = 0;
    }

    // Epilogue: bias + GLU. acc cols (0,1)=(a,gate) for pair p, (2,3) row+8.
#pragma unroll
    for (int mt = 0; mt < 2; mt++) {
        int row = m0 + warpM * 32 + mt * 16 + (lane >> 2);
#pragma unroll
        for (int nt = 0; nt < 8; nt++) {
            int col = nb0 + warpN * 32 + nt * 4 + (lane & 3);
            float ba = __ldg(bias + col);
            float bg = __ldg(bias + NHALF + col);

            float za0 = acc[mt][nt][0] + ba;
            float zg0 = acc[mt][nt][1] + bg;
            out[(size_t)row * NHALF + col] = za0 * (1.f / (1.f + __expf(-zg0)));

            float za1 = acc[mt][nt][2] + ba;
            float zg1 = acc[mt][nt][3] + bg;
            out[(size_t)(row + 8) * NHALF + col] = za1 * (1.f / (1.f + __expf(-zg1)));
        }
    }
}

// ---------------------------------------------------------------------------
extern "C" void kernel_launch(void* const* d_in, const int* in_sizes, int n_in,
                              void* d_out, int out_size)
{
    const float* u    = (const float*)d_in[0];  // [2,4096,2048]
    const float* kern = (const float*)d_in[1];  // [1,2048,128]
    const float* D    = (const float*)d_in[2];  // [1,2048]
    const float* W    = (const float*)d_in[3];  // [4096,2048]
    const float* bias = (const float*)d_in[4];  // [4096]
    float* out = (float*)d_out;                 // [2,4096,2048]

    cudaFuncSetAttribute(gemm_glu_f16, cudaFuncAttributeMaxDynamicSharedMemorySize, SMEM_TOTAL_G);

    wconv_kernel<<<8192, 256>>>(W);
    conv_gelu_kernel<<<dim3(LL / 64, HH / 32, BB), 256>>>(u, kern, D);
    // 32 pair-col tiles (64 cols each) x 64 M-tiles (128 rows each)
    gemm_glu_f16<<<dim3(NHALF / 64, (BB * LL) / 128), 256, SMEM_TOTAL_G>>>(bias, out);
}

// round 6
// speedup vs baseline: 2.1243x; 1.0052x over previous
#include <cuda_runtime.h>
#include <cuda_fp16.h>
#include <cstdint>
#include <math.h>

// Problem constants
#define BB 2
#define LL 4096
#define HH 2048
#define LK 128
#define KDIM HH          // GEMM K = H = 2048
#define NHALF HH         // GLU half width = 2048

typedef unsigned long long u64b;

// Scratch (static __device__ arrays: allocation-free per harness rules)
__device__ __half g_buf[(size_t)BB * LL * HH];   // gelu(conv) output fp16, [M=B*L, K=H]
__device__ __half w_h[(size_t)2 * HH * HH];      // W fp16, [4096, 2048]

__device__ __forceinline__ void cp_async16(void* smem_ptr, const void* gptr) {
    uint32_t s = (uint32_t)__cvta_generic_to_shared(smem_ptr);
    asm volatile("cp.async.cg.shared.global [%0], [%1], 16;\n" :: "r"(s), "l"(gptr));
}
__device__ __forceinline__ void cp_commit() { asm volatile("cp.async.commit_group;\n"); }
template <int N>
__device__ __forceinline__ void cp_wait() { asm volatile("cp.async.wait_group %0;\n" :: "n"(N)); }

__device__ __forceinline__ void ldsm_x4(uint32_t& r0, uint32_t& r1, uint32_t& r2, uint32_t& r3,
                                        uint32_t addr) {
    asm volatile("ldmatrix.sync.aligned.m8n8.x4.shared.b16 {%0,%1,%2,%3}, [%4];"
                 : "=r"(r0), "=r"(r1), "=r"(r2), "=r"(r3) : "r"(addr));
}

__device__ __forceinline__ void mma_f16(float* c, const uint32_t* a, const uint32_t* b) {
    asm volatile(
        "mma.sync.aligned.m16n8k16.row.col.f32.f16.f16.f32 "
        "{%0,%1,%2,%3}, {%4,%5,%6,%7}, {%8,%9}, {%0,%1,%2,%3};\n"
        : "+f"(c[0]), "+f"(c[1]), "+f"(c[2]), "+f"(c[3])
        : "r"(a[0]), "r"(a[1]), "r"(a[2]), "r"(a[3]), "r"(b[0]), "r"(b[1]));
}

__device__ __forceinline__ uint32_t h2_bits(__half2 h) {
    union { __half2 h; uint32_t u; } cvt;
    cvt.h = h;
    return cvt.u;
}

// Packed fp32x2 helpers (Blackwell FFMA2 path)
__device__ __forceinline__ void fma2(u64b& d, u64b a, u64b b, u64b c) {
    asm("fma.rn.f32x2 %0, %1, %2, %3;" : "=l"(d) : "l"(a), "l"(b), "l"(c));
}
__device__ __forceinline__ u64b pack2(float lo, float hi) {
    u64b p;
    asm("mov.b64 %0, {%1, %2};" : "=l"(p) : "f"(lo), "f"(hi));
    return p;
}
__device__ __forceinline__ void unpack2(float& lo, float& hi, u64b v) {
    asm("mov.b64 {%0, %1}, %2;" : "=f"(lo), "=f"(hi) : "l"(v));
}

// ---------------------------------------------------------------------------
// Kernel 0: W -> fp16
// ---------------------------------------------------------------------------
__global__ void wconv_kernel(const float* __restrict__ W) {
    size_t i = ((size_t)blockIdx.x * 256 + threadIdx.x) * 4;
    float4 v = *(const float4*)(W + i);
    uint2 o;
    o.x = h2_bits(__floats2half2_rn(v.x, v.y));
    o.y = h2_bits(__floats2half2_rn(v.z, v.w));
    *(uint2*)(w_h + i) = o;
}

// ---------------------------------------------------------------------------
// Kernel 1: causal long-conv + 2*D*u + exact GELU, packed f32x2 over h-pairs.
// Tile: 64 l x 64 h (32 h-pairs) per block, 256 threads, 8 l-outputs/thread.
// smem as u64 so LDS.64 feeds fma.rn.f32x2 directly (no pack in inner loop).
// Dynamic smem: ks2 128*32 + us2 191*32 u64 = 81664 B.
// ---------------------------------------------------------------------------
#define CONV_SMEM ((128 * 32 + 191 * 32) * 8)

__global__ __launch_bounds__(256) void conv_gelu_f32x2(
    const float* __restrict__ u, const float* __restrict__ kern,
    const float* __restrict__ D, int b, int l_base)
{
    extern __shared__ u64b sm2[];
    u64b* ks2 = sm2;               // [j=128][hp=32]
    u64b* us2 = sm2 + 128 * 32;    // [t=191][hp=32]

    const int l0 = l_base + blockIdx.x * 64;
    const int h0 = blockIdx.y * 64;
    const int tid = threadIdx.x;

    // Kernel taps: squash + pack h-pairs (j contiguous across lanes -> coalesced)
    for (int idx = tid; idx < 128 * 32; idx += 256) {
        int hp = idx >> 7, j = idx & 127;
        int h = h0 + 2 * hp;
        float v0 = kern[h * LK + j], v1 = kern[(h + 1) * LK + j];
        float a0 = fabsf(v0) - 0.003f; a0 = (a0 > 0.f) ? copysignf(a0, v0) : 0.f;
        float a1 = fabsf(v1) - 0.003f; a1 = (a1 > 0.f) ? copysignf(a1, v1) : 0.f;
        ks2[j * 32 + hp] = pack2(a0, a1);
    }
    // u window: 64-bit loads of adjacent h pairs, coalesced
    const float* ub = u + (size_t)b * LL * HH;
    for (int idx = tid; idx < 191 * 32; idx += 256) {
        int t = idx >> 5, hp = idx & 31;
        int gl = l0 - (LK - 1) + t;
        u64b val = 0ull;
        if (gl >= 0) val = *(const u64b*)(ub + (size_t)gl * HH + h0 + 2 * hp);
        us2[t * 32 + hp] = val;
    }
    __syncthreads();

    const int tx = tid & 31;       // h-pair lane
    const int ty = tid >> 5;
    const int lyb = ty * 8;

    u64b acc[8];
#pragma unroll
    for (int i = 0; i < 8; i++) acc[i] = 0ull;

    for (int j = 0; j < LK; j += 8) {
        u64b kr[8];
#pragma unroll
        for (int jj = 0; jj < 8; jj++) kr[jj] = ks2[(j + jj) * 32 + tx];
        u64b w[15];
        const int tb = 120 + lyb - j;
#pragma unroll
        for (int s = 0; s < 15; s++) w[s] = us2[(tb + s) * 32 + tx];
#pragma unroll
        for (int jj = 0; jj < 8; jj++)
#pragma unroll
            for (int i = 0; i < 8; i++)
                fma2(acc[i], kr[jj], w[7 - jj + i], acc[i]);
    }

    const int h = h0 + 2 * tx;
    const u64b Dv2 = pack2(2.f * D[h], 2.f * D[h + 1]);
#pragma unroll
    for (int i = 0; i < 8; i++) {
        int ly = lyb + i;
        u64b y2;
        fma2(y2, Dv2, us2[(LK - 1 + ly) * 32 + tx], acc[i]);
        float y0, y1;
        unpack2(y0, y1, y2);
        float g0 = y0 * normcdff(y0);
        float g1 = y1 * normcdff(y1);
        *(uint32_t*)(g_buf + ((size_t)b * LL + l0 + ly) * HH + h) =
            h2_bits(__floats2half2_rn(g0, g1));
    }
}

// ---------------------------------------------------------------------------
// Kernel 2: FP16 mma.sync GEMM + fused GLU epilogue (per M-chunk).
//   CTA tile: M=128 x 128 B-rows (64 GLU pairs) x K=2048.
//   B rows interleave a/gate halves of W => acc cols (2c,2c+1) = (a,gate).
// ---------------------------------------------------------------------------
#define KST 64                       // k elements per stage (128 B/row)
#define STG_BYTES 16384              // 128 rows * 128 B
#define ST_A 0
#define ST_B (3 * STG_BYTES)
#define SMEM_TOTAL_G (6 * STG_BYTES) // 96 KB

__device__ __forceinline__ uint32_t sw128(uint32_t off) {
    return off ^ ((off >> 3) & 0x70);
}

__global__ __launch_bounds__(256, 2) void gemm_glu_f16(
    const float* __restrict__ bias, float* __restrict__ out, int m_base)
{
    extern __shared__ char smem[];
    const uint32_t sb = (uint32_t)__cvta_generic_to_shared(smem);
    const int tid  = threadIdx.x;
    const int lane = tid & 31;
    const int wid  = tid >> 5;
    const int warpM = wid & 3;
    const int warpN = wid >> 2;
    const int m0  = m_base + blockIdx.y * 128;
    const int nb0 = blockIdx.x * 64;

    auto load_stage = [&](int slot, int k0) {
#pragma unroll
        for (int i = 0; i < 8; i++) {
            int idx = tid + i * 256;
            int row = (idx >> 3) & 127, ch = idx & 7;
            uint32_t sw = sw128(row * 128 + ch * 16);
            if (idx < 1024) {
                cp_async16(smem + ST_A + slot * STG_BYTES + sw,
                           g_buf + (size_t)(m0 + row) * KDIM + k0 + ch * 8);
            } else {
                int q = row >> 1;
                int wrow = (row & 1) ? (NHALF + nb0 + q) : (nb0 + q);
                cp_async16(smem + ST_B + slot * STG_BYTES + sw,
                           w_h + (size_t)wrow * KDIM + k0 + ch * 8);
            }
        }
        cp_commit();
    };

    float acc[2][8][4];
#pragma unroll
    for (int mt = 0; mt < 2; mt++)
#pragma unroll
        for (int nt = 0; nt < 8; nt++)
#pragma unroll
            for (int c = 0; c < 4; c++) acc[mt][nt][c] = 0.f;

    const int NST = KDIM / KST;              // 32
    load_stage(0, 0);
    load_stage(1, KST);

    const uint32_t a_row = warpM * 32 + (lane & 15);
    const uint32_t a_kh8 = (lane >> 4) << 3;
    const uint32_t b_row = warpN * 64 + (lane & 7) + ((lane >> 4) << 3);
    const uint32_t b_kh8 = lane & 8;

    int slot = 0;
    for (int s = 0; s < NST; s++) {
        cp_wait<1>();
        __syncthreads();

        if (s + 2 < NST) {
            int ls = slot + 2; if (ls >= 3) ls -= 3;
            load_stage(ls, (s + 2) * KST);
        }

        const uint32_t abase = sb + ST_A + slot * STG_BYTES;
        const uint32_t bbase = sb + ST_B + slot * STG_BYTES;

#pragma unroll
        for (int k16 = 0; k16 < 4; k16++) {
            const uint32_t kk = k16 * 16;
            uint32_t a[2][4], bf[8][2];
#pragma unroll
            for (int mt = 0; mt < 2; mt++)
                ldsm_x4(a[mt][0], a[mt][1], a[mt][2], a[mt][3],
                        abase + sw128((a_row + mt * 16) * 128 + (kk + a_kh8) * 2));
#pragma unroll
            for (int nt2 = 0; nt2 < 4; nt2++)
                ldsm_x4(bf[2 * nt2][0], bf[2 * nt2][1], bf[2 * nt2 + 1][0], bf[2 * nt2 + 1][1],
                        bbase + sw128((b_row + nt2 * 16) * 128 + (kk + b_kh8) * 2));
#pragma unroll
            for (int mt = 0; mt < 2; mt++)
#pragma unroll
                for (int nt = 0; nt < 8; nt++)
                    mma_f16(acc[mt][nt], a[mt], bf[nt]);
        }

        if (++slot >= 3) slot = 0;
    }

#pragma unroll
    for (int mt = 0; mt < 2; mt++) {
        int row = m0 + warpM * 32 + mt * 16 + (lane >> 2);
#pragma unroll
        for (int nt = 0; nt < 8; nt++) {
            int col = nb0 + warpN * 32 + nt * 4 + (lane & 3);
            float ba = __ldg(bias + col);
            float bg = __ldg(bias + NHALF + col);

            float za0 = acc[mt][nt][0] + ba;
            float zg0 = acc[mt][nt][1] + bg;
            out[(size_t)row * NHALF + col] = za0 * (1.f / (1.f + __expf(-zg0)));

            float za1 = acc[mt][nt][2] + ba;
            float zg1 = acc[mt][nt][3] + bg;
            out[(size_t)(row + 8) * NHALF + col] = za1 * (1.f / (1.f + __expf(-zg1)));
        }
    }
}

// ---------------------------------------------------------------------------
// Launch: conv chunks on the legacy stream, GEMM chunks on a second stream
// gated by events, so conv(c+1..) overlaps gemm(c). Stream/events created
// lazily on the (uncaptured) correctness call; captured calls replay the
// identical fork/join pattern.
// ---------------------------------------------------------------------------
#define NCHUNK 4
#define MCHUNK ((BB * LL) / NCHUNK)   // 2048 rows

extern "C" void kernel_launch(void* const* d_in, const int* in_sizes, int n_in,
                              void* d_out, int out_size)
{
    const float* u    = (const float*)d_in[0];  // [2,4096,2048]
    const float* kern = (const float*)d_in[1];  // [1,2048,128]
    const float* D    = (const float*)d_in[2];  // [1,2048]
    const float* W    = (const float*)d_in[3];  // [4096,2048]
    const float* bias = (const float*)d_in[4];  // [4096]
    float* out = (float*)d_out;                 // [2,4096,2048]

    static cudaStream_t s_gemm = nullptr;
    static cudaEvent_t ev_conv[NCHUNK];
    static cudaEvent_t ev_done;
    if (s_gemm == nullptr) {
        cudaStreamCreateWithFlags(&s_gemm, cudaStreamNonBlocking);
        for (int c = 0; c < NCHUNK; c++)
            cudaEventCreateWithFlags(&ev_conv[c], cudaEventDisableTiming);
        cudaEventCreateWithFlags(&ev_done, cudaEventDisableTiming);
        cudaFuncSetAttribute(gemm_glu_f16, cudaFuncAttributeMaxDynamicSharedMemorySize,
                             SMEM_TOTAL_G);
        cudaFuncSetAttribute(conv_gelu_f32x2, cudaFuncAttributeMaxDynamicSharedMemorySize,
                             CONV_SMEM);
    }

    wconv_kernel<<<8192, 256>>>(W);

    for (int c = 0; c < NCHUNK; c++) {
        int b = c >> 1;
        int l_base = (c & 1) * MCHUNK;   // MCHUNK == LL/2
        conv_gelu_f32x2<<<dim3(MCHUNK / 64, HH / 64), 256, CONV_SMEM>>>(u, kern, D, b, l_base);
        cudaEventRecord(ev_conv[c], 0);
    }

    for (int c = 0; c < NCHUNK; c++) {
        cudaStreamWaitEvent(s_gemm, ev_conv[c], 0);
        gemm_glu_f16<<<dim3(NHALF / 64, MCHUNK / 128), 256, SMEM_TOTAL_G, s_gemm>>>(
            bias, out, c * MCHUNK);
    }

    cudaEventRecord(ev_done, s_gemm);
    cudaStreamWaitEvent(0, ev_done, 0);
}

// round 7
// speedup vs baseline: 2.1293x; 1.0024x over previous
#include <cuda_runtime.h>
#include <cuda_fp16.h>
#include <cstdint>
#include <math.h>

// Problem constants
#define BB 2
#define LL 4096
#define HH 2048
#define LK 128
#define KDIM HH          // GEMM K = H = 2048
#define NHALF HH         // GLU half width = 2048

typedef unsigned long long u64b;

// Scratch (static __device__ arrays: allocation-free per harness rules)
__device__ __half g_buf[(size_t)BB * LL * HH];   // gelu(conv) output fp16, [M=B*L, K=H]
__device__ __half w_h[(size_t)2 * HH * HH];      // W fp16, [4096, 2048]

__device__ __forceinline__ void cp_async16(void* smem_ptr, const void* gptr) {
    uint32_t s = (uint32_t)__cvta_generic_to_shared(smem_ptr);
    asm volatile("cp.async.cg.shared.global [%0], [%1], 16;\n" :: "r"(s), "l"(gptr));
}
__device__ __forceinline__ void cp_commit() { asm volatile("cp.async.commit_group;\n"); }
template <int N>
__device__ __forceinline__ void cp_wait() { asm volatile("cp.async.wait_group %0;\n" :: "n"(N)); }

__device__ __forceinline__ void ldsm_x4(uint32_t& r0, uint32_t& r1, uint32_t& r2, uint32_t& r3,
                                        uint32_t addr) {
    asm volatile("ldmatrix.sync.aligned.m8n8.x4.shared.b16 {%0,%1,%2,%3}, [%4];"
                 : "=r"(r0), "=r"(r1), "=r"(r2), "=r"(r3) : "r"(addr));
}

__device__ __forceinline__ void mma_f16(float* c, const uint32_t* a, const uint32_t* b) {
    asm volatile(
        "mma.sync.aligned.m16n8k16.row.col.f32.f16.f16.f32 "
        "{%0,%1,%2,%3}, {%4,%5,%6,%7}, {%8,%9}, {%0,%1,%2,%3};\n"
        : "+f"(c[0]), "+f"(c[1]), "+f"(c[2]), "+f"(c[3])
        : "r"(a[0]), "r"(a[1]), "r"(a[2]), "r"(a[3]), "r"(b[0]), "r"(b[1]));
}

__device__ __forceinline__ uint32_t h2_bits(__half2 h) {
    union { __half2 h; uint32_t u; } cvt;
    cvt.h = h;
    return cvt.u;
}

// Packed fp32x2 helpers (Blackwell FFMA2 path)
__device__ __forceinline__ void fma2(u64b& d, u64b a, u64b b, u64b c) {
    asm("fma.rn.f32x2 %0, %1, %2, %3;" : "=l"(d) : "l"(a), "l"(b), "l"(c));
}
__device__ __forceinline__ u64b pack2(float lo, float hi) {
    u64b p;
    asm("mov.b64 %0, {%1, %2};" : "=l"(p) : "f"(lo), "f"(hi));
    return p;
}
__device__ __forceinline__ void unpack2(float& lo, float& hi, u64b v) {
    asm("mov.b64 {%0, %1}, %2;" : "=f"(lo), "=f"(hi) : "l"(v));
}

// ---------------------------------------------------------------------------
// Kernel 0: W -> fp16
// ---------------------------------------------------------------------------
__global__ void wconv_kernel(const float* __restrict__ W) {
    size_t i = ((size_t)blockIdx.x * 256 + threadIdx.x) * 4;
    float4 v = *(const float4*)(W + i);
    uint2 o;
    o.x = h2_bits(__floats2half2_rn(v.x, v.y));
    o.y = h2_bits(__floats2half2_rn(v.z, v.w));
    *(uint2*)(w_h + i) = o;
}

// ---------------------------------------------------------------------------
// Kernel 1 (v3): causal long-conv + 2*D*u + exact GELU, packed f32x2.
// Tile: 64 l x 64 h (32 h-pairs), 128 threads, SIXTEEN l-outputs/thread.
// Per j-block of 8: 31 LDS.64 feed 128 FFMA2 (1.94 B/FFMA2) -> smem crossbar
// and FFMA2-issue floors balanced.
// ---------------------------------------------------------------------------
#define CONV_SMEM ((128 * 32 + 191 * 32) * 8)

__global__ __launch_bounds__(128) void conv_gelu_f32x2(
    const float* __restrict__ u, const float* __restrict__ kern,
    const float* __restrict__ D, int b, int l_base)
{
    extern __shared__ u64b sm2[];
    u64b* ks2 = sm2;               // [j=128][hp=32]
    u64b* us2 = sm2 + 128 * 32;    // [t=191][hp=32]

    const int l0 = l_base + blockIdx.x * 64;
    const int h0 = blockIdx.y * 64;
    const int tid = threadIdx.x;

    // Kernel taps: squash + pack h-pairs (j contiguous across lanes -> coalesced)
    for (int idx = tid; idx < 128 * 32; idx += 128) {
        int hp = idx >> 7, j = idx & 127;
        int h = h0 + 2 * hp;
        float v0 = kern[h * LK + j], v1 = kern[(h + 1) * LK + j];
        float a0 = fabsf(v0) - 0.003f; a0 = (a0 > 0.f) ? copysignf(a0, v0) : 0.f;
        float a1 = fabsf(v1) - 0.003f; a1 = (a1 > 0.f) ? copysignf(a1, v1) : 0.f;
        ks2[j * 32 + hp] = pack2(a0, a1);
    }
    // u window: 64-bit loads of adjacent h pairs, coalesced
    const float* ub = u + (size_t)b * LL * HH;
    for (int idx = tid; idx < 191 * 32; idx += 128) {
        int t = idx >> 5, hp = idx & 31;
        int gl = l0 - (LK - 1) + t;
        u64b val = 0ull;
        if (gl >= 0) val = *(const u64b*)(ub + (size_t)gl * HH + h0 + 2 * hp);
        us2[t * 32 + hp] = val;
    }
    __syncthreads();

    const int tx = tid & 31;       // h-pair lane
    const int ty = tid >> 5;       // 0..3
    const int lyb = ty * 16;

    u64b acc[16];
#pragma unroll
    for (int i = 0; i < 16; i++) acc[i] = 0ull;

    for (int j = 0; j < LK; j += 8) {
        u64b kr[8];
#pragma unroll
        for (int jj = 0; jj < 8; jj++) kr[jj] = ks2[(j + jj) * 32 + tx];
        u64b w[23];
        const int tb = 120 + lyb - j;  // t for s=0
#pragma unroll
        for (int s = 0; s < 23; s++) w[s] = us2[(tb + s) * 32 + tx];
#pragma unroll
        for (int jj = 0; jj < 8; jj++)
#pragma unroll
            for (int i = 0; i < 16; i++)
                fma2(acc[i], kr[jj], w[7 - jj + i], acc[i]);
    }

    const int h = h0 + 2 * tx;
    const u64b Dv2 = pack2(2.f * D[h], 2.f * D[h + 1]);
#pragma unroll
    for (int i = 0; i < 16; i++) {
        int ly = lyb + i;
        u64b y2;
        fma2(y2, Dv2, us2[(LK - 1 + ly) * 32 + tx], acc[i]);
        float y0, y1;
        unpack2(y0, y1, y2);
        float g0 = y0 * normcdff(y0);
        float g1 = y1 * normcdff(y1);
        *(uint32_t*)(g_buf + ((size_t)b * LL + l0 + ly) * HH + h) =
            h2_bits(__floats2half2_rn(g0, g1));
    }
}

// ---------------------------------------------------------------------------
// Kernel 2: FP16 mma.sync GEMM + fused GLU epilogue (per M-chunk).
//   CTA tile: M=128 x 128 B-rows (64 GLU pairs) x K=2048.
//   B rows interleave a/gate halves of W => acc cols (2c,2c+1) = (a,gate).
// ---------------------------------------------------------------------------
#define KST 64                       // k elements per stage (128 B/row)
#define STG_BYTES 16384              // 128 rows * 128 B
#define ST_A 0
#define ST_B (3 * STG_BYTES)
#define SMEM_TOTAL_G (6 * STG_BYTES) // 96 KB

__device__ __forceinline__ uint32_t sw128(uint32_t off) {
    return off ^ ((off >> 3) & 0x70);
}

__global__ __launch_bounds__(256, 2) void gemm_glu_f16(
    const float* __restrict__ bias, float* __restrict__ out, int m_base)
{
    extern __shared__ char smem[];
    const uint32_t sb = (uint32_t)__cvta_generic_to_shared(smem);
    const int tid  = threadIdx.x;
    const int lane = tid & 31;
    const int wid  = tid >> 5;
    const int warpM = wid & 3;
    const int warpN = wid >> 2;
    const int m0  = m_base + blockIdx.y * 128;
    const int nb0 = blockIdx.x * 64;

    auto load_stage = [&](int slot, int k0) {
#pragma unroll
        for (int i = 0; i < 8; i++) {
            int idx = tid + i * 256;
            int row = (idx >> 3) & 127, ch = idx & 7;
            uint32_t sw = sw128(row * 128 + ch * 16);
            if (idx < 1024) {
                cp_async16(smem + ST_A + slot * STG_BYTES + sw,
                           g_buf + (size_t)(m0 + row) * KDIM + k0 + ch * 8);
            } else {
                int q = row >> 1;
                int wrow = (row & 1) ? (NHALF + nb0 + q) : (nb0 + q);
                cp_async16(smem + ST_B + slot * STG_BYTES + sw,
                           w_h + (size_t)wrow * KDIM + k0 + ch * 8);
            }
        }
        cp_commit();
    };

    float acc[2][8][4];
#pragma unroll
    for (int mt = 0; mt < 2; mt++)
#pragma unroll
        for (int nt = 0; nt < 8; nt++)
#pragma unroll
            for (int c = 0; c < 4; c++) acc[mt][nt][c] = 0.f;

    const int NST = KDIM / KST;              // 32
    load_stage(0, 0);
    load_stage(1, KST);

    const uint32_t a_row = warpM * 32 + (lane & 15);
    const uint32_t a_kh8 = (lane >> 4) << 3;
    const uint32_t b_row = warpN * 64 + (lane & 7) + ((lane >> 4) << 3);
    const uint32_t b_kh8 = lane & 8;

    int slot = 0;
    for (int s = 0; s < NST; s++) {
        cp_wait<1>();
        __syncthreads();

        if (s + 2 < NST) {
            int ls = slot + 2; if (ls >= 3) ls -= 3;
            load_stage(ls, (s + 2) * KST);
        }

        const uint32_t abase = sb + ST_A + slot * STG_BYTES;
        const uint32_t bbase = sb + ST_B + slot * STG_BYTES;

#pragma unroll
        for (int k16 = 0; k16 < 4; k16++) {
            const uint32_t kk = k16 * 16;
            uint32_t a[2][4], bf[8][2];
#pragma unroll
            for (int mt = 0; mt < 2; mt++)
                ldsm_x4(a[mt][0], a[mt][1], a[mt][2], a[mt][3],
                        abase + sw128((a_row + mt * 16) * 128 + (kk + a_kh8) * 2));
#pragma unroll
            for (int nt2 = 0; nt2 < 4; nt2++)
                ldsm_x4(bf[2 * nt2][0], bf[2 * nt2][1], bf[2 * nt2 + 1][0], bf[2 * nt2 + 1][1],
                        bbase + sw128((b_row + nt2 * 16) * 128 + (kk + b_kh8) * 2));
#pragma unroll
            for (int mt = 0; mt < 2; mt++)
#pragma unroll
                for (int nt = 0; nt < 8; nt++)
                    mma_f16(acc[mt][nt], a[mt], bf[nt]);
        }

        if (++slot >= 3) slot = 0;
    }

#pragma unroll
    for (int mt = 0; mt < 2; mt++) {
        int row = m0 + warpM * 32 + mt * 16 + (lane >> 2);
#pragma unroll
        for (int nt = 0; nt < 8; nt++) {
            int col = nb0 + warpN * 32 + nt * 4 + (lane & 3);
            float ba = __ldg(bias + col);
            float bg = __ldg(bias + NHALF + col);

            float za0 = acc[mt][nt][0] + ba;
            float zg0 = acc[mt][nt][1] + bg;
            out[(size_t)row * NHALF + col] = za0 * (1.f / (1.f + __expf(-zg0)));

            float za1 = acc[mt][nt][2] + ba;
            float zg1 = acc[mt][nt][3] + bg;
            out[(size_t)(row + 8) * NHALF + col] = za1 * (1.f / (1.f + __expf(-zg1)));
        }
    }
}

// ---------------------------------------------------------------------------
// Launch: 2 chunks (one per batch). conv on legacy stream, GEMM on a second
// stream gated by events (tail overlap only — smem keeps them from co-residing,
// but the event fork/join is capture-safe and costs nothing).
// ---------------------------------------------------------------------------
#define NCHUNK 2
#define MCHUNK ((BB * LL) / NCHUNK)   // 4096 rows = one batch

extern "C" void kernel_launch(void* const* d_in, const int* in_sizes, int n_in,
                              void* d_out, int out_size)
{
    const float* u    = (const float*)d_in[0];  // [2,4096,2048]
    const float* kern = (const float*)d_in[1];  // [1,2048,128]
    const float* D    = (const float*)d_in[2];  // [1,2048]
    const float* W    = (const float*)d_in[3];  // [4096,2048]
    const float* bias = (const float*)d_in[4];  // [4096]
    float* out = (float*)d_out;                 // [2,4096,2048]

    static cudaStream_t s_gemm = nullptr;
    static cudaEvent_t ev_conv[NCHUNK];
    static cudaEvent_t ev_done;
    if (s_gemm == nullptr) {
        cudaStreamCreateWithFlags(&s_gemm, cudaStreamNonBlocking);
        for (int c = 0; c < NCHUNK; c++)
            cudaEventCreateWithFlags(&ev_conv[c], cudaEventDisableTiming);
        cudaEventCreateWithFlags(&ev_done, cudaEventDisableTiming);
        cudaFuncSetAttribute(gemm_glu_f16, cudaFuncAttributeMaxDynamicSharedMemorySize,
                             SMEM_TOTAL_G);
        cudaFuncSetAttribute(conv_gelu_f32x2, cudaFuncAttributeMaxDynamicSharedMemorySize,
                             CONV_SMEM);
    }

    wconv_kernel<<<8192, 256>>>(W);

    for (int c = 0; c < NCHUNK; c++) {
        conv_gelu_f32x2<<<dim3(LL / 64, HH / 64), 128, CONV_SMEM>>>(u, kern, D, c, 0);
        cudaEventRecord(ev_conv[c], 0);
    }

    for (int c = 0; c < NCHUNK; c++) {
        cudaStreamWaitEvent(s_gemm, ev_conv[c], 0);
        gemm_glu_f16<<<dim3(NHALF / 64, MCHUNK / 128), 256, SMEM_TOTAL_G, s_gemm>>>(
            bias, out, c * MCHUNK);
    }

    cudaEventRecord(ev_done, s_gemm);
    cudaStreamWaitEvent(0, ev_done, 0);
}

// round 8
// speedup vs baseline: 2.1745x; 1.0212x over previous
#include <cuda_runtime.h>
#include <cuda_fp16.h>
#include <cstdint>
#include <math.h>

// Problem constants
#define BB 2
#define LL 4096
#define HH 2048
#define LK 128
#define KDIM HH          // GEMM K = H = 2048
#define NHALF HH         // GLU half width = 2048

typedef unsigned long long u64b;

// Scratch (static __device__ arrays: allocation-free per harness rules)
__device__ __half g_buf[(size_t)BB * LL * HH];   // gelu(conv) output fp16, [M=B*L, K=H]
__device__ __half w_h[(size_t)2 * HH * HH];      // W fp16, [4096, 2048]

__device__ __forceinline__ void cp_async16(void* smem_ptr, const void* gptr) {
    uint32_t s = (uint32_t)__cvta_generic_to_shared(smem_ptr);
    asm volatile("cp.async.cg.shared.global [%0], [%1], 16;\n" :: "r"(s), "l"(gptr));
}
__device__ __forceinline__ void cp_commit() { asm volatile("cp.async.commit_group;\n"); }
template <int N>
__device__ __forceinline__ void cp_wait() { asm volatile("cp.async.wait_group %0;\n" :: "n"(N)); }

__device__ __forceinline__ void ldsm_x4(uint32_t& r0, uint32_t& r1, uint32_t& r2, uint32_t& r3,
                                        uint32_t addr) {
    asm volatile("ldmatrix.sync.aligned.m8n8.x4.shared.b16 {%0,%1,%2,%3}, [%4];"
                 : "=r"(r0), "=r"(r1), "=r"(r2), "=r"(r3) : "r"(addr));
}

__device__ __forceinline__ void mma_f16(float* c, const uint32_t* a, const uint32_t* b) {
    asm volatile(
        "mma.sync.aligned.m16n8k16.row.col.f32.f16.f16.f32 "
        "{%0,%1,%2,%3}, {%4,%5,%6,%7}, {%8,%9}, {%0,%1,%2,%3};\n"
        : "+f"(c[0]), "+f"(c[1]), "+f"(c[2]), "+f"(c[3])
        : "r"(a[0]), "r"(a[1]), "r"(a[2]), "r"(a[3]), "r"(b[0]), "r"(b[1]));
}

__device__ __forceinline__ uint32_t h2_bits(__half2 h) {
    union { __half2 h; uint32_t u; } cvt;
    cvt.h = h;
    return cvt.u;
}

// Packed fp32x2 helpers (Blackwell FFMA2 path)
__device__ __forceinline__ void fma2(u64b& d, u64b a, u64b b, u64b c) {
    asm("fma.rn.f32x2 %0, %1, %2, %3;" : "=l"(d) : "l"(a), "l"(b), "l"(c));
}
__device__ __forceinline__ u64b pack2(float lo, float hi) {
    u64b p;
    asm("mov.b64 %0, {%1, %2};" : "=l"(p) : "f"(lo), "f"(hi));
    return p;
}
__device__ __forceinline__ void unpack2(float& lo, float& hi, u64b v) {
    asm("mov.b64 {%0, %1}, %2;" : "=f"(lo), "=f"(hi) : "l"(v));
}

// ---------------------------------------------------------------------------
// Kernel 0: W -> fp16
// ---------------------------------------------------------------------------
__global__ void wconv_kernel(const float* __restrict__ W) {
    size_t i = ((size_t)blockIdx.x * 256 + threadIdx.x) * 4;
    float4 v = *(const float4*)(W + i);
    uint2 o;
    o.x = h2_bits(__floats2half2_rn(v.x, v.y));
    o.y = h2_bits(__floats2half2_rn(v.z, v.w));
    *(uint2*)(w_h + i) = o;
}

// ---------------------------------------------------------------------------
// Kernel 1 (v4): conv + 2*D*u + exact GELU, packed f32x2.
// Tile: 128 l x 32 h (16 h-pairs), 128 threads, 16 l-outputs/thread.
// smem 49 KB -> 4 CTAs/SM (4 warps/SMSP latency hiding, 2x v3).
// ---------------------------------------------------------------------------
#define CONV_SMEM ((128 * 16 + 255 * 16) * 8)   // 49024 B

__global__ __launch_bounds__(128, 4) void conv_gelu_f32x2(
    const float* __restrict__ u, const float* __restrict__ kern,
    const float* __restrict__ D, int b)
{
    extern __shared__ u64b sm2[];
    u64b* ks2 = sm2;               // [j=128][hp=16]
    u64b* us2 = sm2 + 128 * 16;    // [t=255][hp=16]

    const int l0 = blockIdx.x * 128;
    const int h0 = blockIdx.y * 32;
    const int tid = threadIdx.x;

    // Kernel taps: squash + pack h-pairs
    for (int idx = tid; idx < 128 * 16; idx += 128) {
        int hp = idx >> 7, j = idx & 127;
        int h = h0 + 2 * hp;
        float v0 = kern[h * LK + j], v1 = kern[(h + 1) * LK + j];
        float a0 = fabsf(v0) - 0.003f; a0 = (a0 > 0.f) ? copysignf(a0, v0) : 0.f;
        float a1 = fabsf(v1) - 0.003f; a1 = (a1 > 0.f) ? copysignf(a1, v1) : 0.f;
        ks2[j * 16 + hp] = pack2(a0, a1);
    }
    // u window [l0-127, l0+127], zero-pad l<0
    const float* ub = u + (size_t)b * LL * HH;
    for (int idx = tid; idx < 255 * 16; idx += 128) {
        int t = idx >> 4, hp = idx & 15;
        int gl = l0 - (LK - 1) + t;
        u64b val = 0ull;
        if (gl >= 0) val = *(const u64b*)(ub + (size_t)gl * HH + h0 + 2 * hp);
        us2[t * 16 + hp] = val;
    }
    __syncthreads();

    const int tx = tid & 15;       // h-pair lane
    const int ty = tid >> 4;       // 0..7
    const int lyb = ty * 16;

    u64b acc[16];
#pragma unroll
    for (int i = 0; i < 16; i++) acc[i] = 0ull;

    for (int j = 0; j < LK; j += 8) {
        u64b kr[8];
#pragma unroll
        for (int jj = 0; jj < 8; jj++) kr[jj] = ks2[(j + jj) * 16 + tx];
        u64b w[23];
        const int tb = 120 + lyb - j;  // t for s=0
#pragma unroll
        for (int s = 0; s < 23; s++) w[s] = us2[(tb + s) * 16 + tx];
#pragma unroll
        for (int jj = 0; jj < 8; jj++)
#pragma unroll
            for (int i = 0; i < 16; i++)
                fma2(acc[i], kr[jj], w[7 - jj + i], acc[i]);
    }

    const int h = h0 + 2 * tx;
    const u64b Dv2 = pack2(2.f * D[h], 2.f * D[h + 1]);
#pragma unroll
    for (int i = 0; i < 16; i++) {
        int ly = lyb + i;
        u64b y2;
        fma2(y2, Dv2, us2[(LK - 1 + ly) * 16 + tx], acc[i]);
        float y0, y1;
        unpack2(y0, y1, y2);
        float g0 = y0 * normcdff(y0);
        float g1 = y1 * normcdff(y1);
        *(uint32_t*)(g_buf + ((size_t)b * LL + l0 + ly) * HH + h) =
            h2_bits(__floats2half2_rn(g0, g1));
    }
}

// ---------------------------------------------------------------------------
// Kernel 2 (v2): FP16 mma.sync GEMM + fused GLU, m64n64 warp tiles.
//   CTA tile: M=128 x 256 B-rows (128 GLU pairs) x K=2048; 1 CTA/SM.
//   8 warps: 2(M) x 4(N), each m64 x n64 -> 32 MMA : 8 LDSM.x4 per k16.
//   B rows interleave a/gate halves of W => acc cols (2c,2c+1) = (a,gate).
//   3-stage cp.async ring (KST=64), one sync/stage, 2-stage lookahead.
// ---------------------------------------------------------------------------
#define KST 64                       // k elements per stage (128 B/row)
#define A_STG 16384                  // 128 rows * 128 B
#define B_STG 32768                  // 256 rows * 128 B
#define ST_A 0
#define ST_B (3 * A_STG)
#define SMEM_TOTAL_G (3 * A_STG + 3 * B_STG)   // 147456 B

__device__ __forceinline__ uint32_t sw128(uint32_t off) {
    return off ^ ((off >> 3) & 0x70);
}

__global__ __launch_bounds__(256, 1) void gemm_glu_f16(
    const float* __restrict__ bias, float* __restrict__ out, int m_base)
{
    extern __shared__ char smem[];
    const uint32_t sb = (uint32_t)__cvta_generic_to_shared(smem);
    const int tid  = threadIdx.x;
    const int lane = tid & 31;
    const int wid  = tid >> 5;
    const int warpM = wid & 1;               // 64 M-rows each
    const int warpN = wid >> 1;              // 64 B-rows each
    const int m0  = m_base + blockIdx.y * 128;
    const int nb0 = blockIdx.x * 128;        // output-pair-column base (256 B-rows)

    auto load_stage = [&](int slot, int k0) {
#pragma unroll
        for (int i = 0; i < 12; i++) {
            int idx = tid + i * 256;
            if (idx < 1024) {
                int row = idx >> 3, ch = idx & 7;
                uint32_t sw = sw128(row * 128 + ch * 16);
                cp_async16(smem + ST_A + slot * A_STG + sw,
                           g_buf + (size_t)(m0 + row) * KDIM + k0 + ch * 8);
            } else {
                int i2 = idx - 1024;
                int row = i2 >> 3, ch = i2 & 7;     // row 0..255
                int q = row >> 1;
                int wrow = (row & 1) ? (NHALF + nb0 + q) : (nb0 + q);
                uint32_t sw = sw128(row * 128 + ch * 16);
                cp_async16(smem + ST_B + slot * B_STG + sw,
                           w_h + (size_t)wrow * KDIM + k0 + ch * 8);
            }
        }
        cp_commit();
    };

    float acc[4][8][4];
#pragma unroll
    for (int mt = 0; mt < 4; mt++)
#pragma unroll
        for (int nt = 0; nt < 8; nt++)
#pragma unroll
            for (int c = 0; c < 4; c++) acc[mt][nt][c] = 0.f;

    const int NST = KDIM / KST;              // 32
    load_stage(0, 0);
    load_stage(1, KST);

    // Per-thread fragment smem offsets (within a stage)
    const uint32_t a_row = warpM * 64 + (lane & 15);
    const uint32_t a_kh8 = (lane >> 4) << 3;                 // 0 or 8
    const uint32_t b_row = warpN * 64 + (lane & 7) + ((lane >> 4) << 3);
    const uint32_t b_kh8 = lane & 8;                         // 0 or 8

    int slot = 0;
    for (int s = 0; s < NST; s++) {
        cp_wait<1>();
        __syncthreads();

        if (s + 2 < NST) {
            int ls = slot + 2; if (ls >= 3) ls -= 3;
            load_stage(ls, (s + 2) * KST);
        }

        const uint32_t abase = sb + ST_A + slot * A_STG;
        const uint32_t bbase = sb + ST_B + slot * B_STG;

#pragma unroll
        for (int k16 = 0; k16 < 4; k16++) {
            const uint32_t kk = k16 * 16;
            uint32_t a[4][4], bf[8][2];
#pragma unroll
            for (int mt = 0; mt < 4; mt++)
                ldsm_x4(a[mt][0], a[mt][1], a[mt][2], a[mt][3],
                        abase + sw128((a_row + mt * 16) * 128 + (kk + a_kh8) * 2));
#pragma unroll
            for (int nt2 = 0; nt2 < 4; nt2++)
                ldsm_x4(bf[2 * nt2][0], bf[2 * nt2][1], bf[2 * nt2 + 1][0], bf[2 * nt2 + 1][1],
                        bbase + sw128((b_row + nt2 * 16) * 128 + (kk + b_kh8) * 2));
#pragma unroll
            for (int mt = 0; mt < 4; mt++)
#pragma unroll
                for (int nt = 0; nt < 8; nt++)
                    mma_f16(acc[mt][nt], a[mt], bf[nt]);
        }

        if (++slot >= 3) slot = 0;
    }

    // Epilogue: bias + GLU. acc cols (0,1)=(a,gate) pair, (2,3) row+8.
#pragma unroll
    for (int mt = 0; mt < 4; mt++) {
        int row = m0 + warpM * 64 + mt * 16 + (lane >> 2);
#pragma unroll
        for (int nt = 0; nt < 8; nt++) {
            int col = nb0 + warpN * 32 + nt * 4 + (lane & 3);
            float ba = __ldg(bias + col);
            float bg = __ldg(bias + NHALF + col);

            float za0 = acc[mt][nt][0] + ba;
            float zg0 = acc[mt][nt][1] + bg;
            out[(size_t)row * NHALF + col] = za0 * (1.f / (1.f + __expf(-zg0)));

            float za1 = acc[mt][nt][2] + ba;
            float zg1 = acc[mt][nt][3] + bg;
            out[(size_t)(row + 8) * NHALF + col] = za1 * (1.f / (1.f + __expf(-zg1)));
        }
    }
}

// ---------------------------------------------------------------------------
// Launch: 2 chunks (one per batch). conv (49KB) and gemm (144KB) can now
// co-reside on an SM, so the cross-stream chunk pipeline can truly overlap.
// ---------------------------------------------------------------------------
#define NCHUNK 2
#define MCHUNK ((BB * LL) / NCHUNK)   // 4096 rows = one batch

extern "C" void kernel_launch(void* const* d_in, const int* in_sizes, int n_in,
                              void* d_out, int out_size)
{
    const float* u    = (const float*)d_in[0];  // [2,4096,2048]
    const float* kern = (const float*)d_in[1];  // [1,2048,128]
    const float* D    = (const float*)d_in[2];  // [1,2048]
    const float* W    = (const float*)d_in[3];  // [4096,2048]
    const float* bias = (const float*)d_in[4];  // [4096]
    float* out = (float*)d_out;                 // [2,4096,2048]

    static cudaStream_t s_gemm = nullptr;
    static cudaEvent_t ev_conv[NCHUNK];
    static cudaEvent_t ev_done;
    if (s_gemm == nullptr) {
        cudaStreamCreateWithFlags(&s_gemm, cudaStreamNonBlocking);
        for (int c = 0; c < NCHUNK; c++)
            cudaEventCreateWithFlags(&ev_conv[c], cudaEventDisableTiming);
        cudaEventCreateWithFlags(&ev_done, cudaEventDisableTiming);
        cudaFuncSetAttribute(gemm_glu_f16, cudaFuncAttributeMaxDynamicSharedMemorySize,
                             SMEM_TOTAL_G);
        cudaFuncSetAttribute(conv_gelu_f32x2, cudaFuncAttributeMaxDynamicSharedMemorySize,
                             CONV_SMEM);
    }

    wconv_kernel<<<8192, 256>>>(W);

    for (int c = 0; c < NCHUNK; c++) {
        conv_gelu_f32x2<<<dim3(LL / 128, HH / 32), 128, CONV_SMEM>>>(u, kern, D, c);
        cudaEventRecord(ev_conv[c], 0);
    }

    for (int c = 0; c < NCHUNK; c++) {
        cudaStreamWaitEvent(s_gemm, ev_conv[c], 0);
        gemm_glu_f16<<<dim3(NHALF / 128, MCHUNK / 128), 256, SMEM_TOTAL_G, s_gemm>>>(
            bias, out, c * MCHUNK);
    }

    cudaEventRecord(ev_done, s_gemm);
    cudaStreamWaitEvent(0, ev_done, 0);
}

// round 9
// speedup vs baseline: 2.4545x; 1.1287x over previous
#include <cuda_runtime.h>
#include <cuda_fp16.h>
#include <cstdint>
#include <math.h>

// Problem constants
#define BB 2
#define LL 4096
#define HH 2048
#define LK 128
#define KDIM HH          // GEMM K = H = 2048
#define NHALF HH         // GLU half width = 2048

typedef unsigned long long u64b;

// Scratch (static __device__ arrays: allocation-free per harness rules)
__device__ __half g_buf[(size_t)BB * LL * HH];   // gelu(conv) output fp16, [M=B*L, K=H]
__device__ __half w_h[(size_t)2 * HH * HH];      // W fp16, [4096, 2048]

__device__ __forceinline__ void cp_async16(void* smem_ptr, const void* gptr) {
    uint32_t s = (uint32_t)__cvta_generic_to_shared(smem_ptr);
    asm volatile("cp.async.cg.shared.global [%0], [%1], 16;\n" :: "r"(s), "l"(gptr));
}
__device__ __forceinline__ void cp_commit() { asm volatile("cp.async.commit_group;\n"); }
template <int N>
__device__ __forceinline__ void cp_wait() { asm volatile("cp.async.wait_group %0;\n" :: "n"(N)); }

__device__ __forceinline__ void ldsm_x4(uint32_t& r0, uint32_t& r1, uint32_t& r2, uint32_t& r3,
                                        uint32_t addr) {
    asm volatile("ldmatrix.sync.aligned.m8n8.x4.shared.b16 {%0,%1,%2,%3}, [%4];"
                 : "=r"(r0), "=r"(r1), "=r"(r2), "=r"(r3) : "r"(addr));
}

__device__ __forceinline__ void mma_f16(float* c, const uint32_t* a, const uint32_t* b) {
    asm volatile(
        "mma.sync.aligned.m16n8k16.row.col.f32.f16.f16.f32 "
        "{%0,%1,%2,%3}, {%4,%5,%6,%7}, {%8,%9}, {%0,%1,%2,%3};\n"
        : "+f"(c[0]), "+f"(c[1]), "+f"(c[2]), "+f"(c[3])
        : "r"(a[0]), "r"(a[1]), "r"(a[2]), "r"(a[3]), "r"(b[0]), "r"(b[1]));
}

__device__ __forceinline__ uint32_t h2_bits(__half2 h) {
    union { __half2 h; uint32_t u; } cvt;
    cvt.h = h;
    return cvt.u;
}

// Packed fp32x2 helpers (Blackwell FFMA2 path)
__device__ __forceinline__ void fma2(u64b& d, u64b a, u64b b, u64b c) {
    asm("fma.rn.f32x2 %0, %1, %2, %3;" : "=l"(d) : "l"(a), "l"(b), "l"(c));
}
__device__ __forceinline__ u64b pack2(float lo, float hi) {
    u64b p;
    asm("mov.b64 %0, {%1, %2};" : "=l"(p) : "f"(lo), "f"(hi));
    return p;
}
__device__ __forceinline__ void unpack2(float& lo, float& hi, u64b v) {
    asm("mov.b64 {%0, %1}, %2;" : "=f"(lo), "=f"(hi) : "l"(v));
}

// ---------------------------------------------------------------------------
// Kernel 0: W -> fp16
// ---------------------------------------------------------------------------
__global__ void wconv_kernel(const float* __restrict__ W) {
    size_t i = ((size_t)blockIdx.x * 256 + threadIdx.x) * 4;
    float4 v = *(const float4*)(W + i);
    uint2 o;
    o.x = h2_bits(__floats2half2_rn(v.x, v.y));
    o.y = h2_bits(__floats2half2_rn(v.z, v.w));
    *(uint2*)(w_h + i) = o;
}

// ---------------------------------------------------------------------------
// Kernel 1 (v4): conv + 2*D*u + exact GELU, packed f32x2.
// Tile: 128 l x 32 h (16 h-pairs), 128 threads, 16 l-outputs/thread.
// smem 49 KB -> 4 CTAs/SM.
// ---------------------------------------------------------------------------
#define CONV_SMEM ((128 * 16 + 255 * 16) * 8)   // 49024 B

__global__ __launch_bounds__(128, 4) void conv_gelu_f32x2(
    const float* __restrict__ u, const float* __restrict__ kern,
    const float* __restrict__ D, int b)
{
    extern __shared__ u64b sm2[];
    u64b* ks2 = sm2;               // [j=128][hp=16]
    u64b* us2 = sm2 + 128 * 16;    // [t=255][hp=16]

    const int l0 = blockIdx.x * 128;
    const int h0 = blockIdx.y * 32;
    const int tid = threadIdx.x;

    for (int idx = tid; idx < 128 * 16; idx += 128) {
        int hp = idx >> 7, j = idx & 127;
        int h = h0 + 2 * hp;
        float v0 = kern[h * LK + j], v1 = kern[(h + 1) * LK + j];
        float a0 = fabsf(v0) - 0.003f; a0 = (a0 > 0.f) ? copysignf(a0, v0) : 0.f;
        float a1 = fabsf(v1) - 0.003f; a1 = (a1 > 0.f) ? copysignf(a1, v1) : 0.f;
        ks2[j * 16 + hp] = pack2(a0, a1);
    }
    const float* ub = u + (size_t)b * LL * HH;
    for (int idx = tid; idx < 255 * 16; idx += 128) {
        int t = idx >> 4, hp = idx & 15;
        int gl = l0 - (LK - 1) + t;
        u64b val = 0ull;
        if (gl >= 0) val = *(const u64b*)(ub + (size_t)gl * HH + h0 + 2 * hp);
        us2[t * 16 + hp] = val;
    }
    __syncthreads();

    const int tx = tid & 15;       // h-pair lane
    const int ty = tid >> 4;       // 0..7
    const int lyb = ty * 16;

    u64b acc[16];
#pragma unroll
    for (int i = 0; i < 16; i++) acc[i] = 0ull;

    for (int j = 0; j < LK; j += 8) {
        u64b kr[8];
#pragma unroll
        for (int jj = 0; jj < 8; jj++) kr[jj] = ks2[(j + jj) * 16 + tx];
        u64b w[23];
        const int tb = 120 + lyb - j;
#pragma unroll
        for (int s = 0; s < 23; s++) w[s] = us2[(tb + s) * 16 + tx];
#pragma unroll
        for (int jj = 0; jj < 8; jj++)
#pragma unroll
            for (int i = 0; i < 16; i++)
                fma2(acc[i], kr[jj], w[7 - jj + i], acc[i]);
    }

    const int h = h0 + 2 * tx;
    const u64b Dv2 = pack2(2.f * D[h], 2.f * D[h + 1]);
#pragma unroll
    for (int i = 0; i < 16; i++) {
        int ly = lyb + i;
        u64b y2;
        fma2(y2, Dv2, us2[(LK - 1 + ly) * 16 + tx], acc[i]);
        float y0, y1;
        unpack2(y0, y1, y2);
        float g0 = y0 * normcdff(y0);
        float g1 = y1 * normcdff(y1);
        *(uint32_t*)(g_buf + ((size_t)b * LL + l0 + ly) * HH + h) =
            h2_bits(__floats2half2_rn(g0, g1));
    }
}

// ---------------------------------------------------------------------------
// Kernel 2 (R7 config — measured best): FP16 mma.sync GEMM + fused GLU.
//   CTA tile: M=128 x 128 B-rows (64 GLU pairs) x K=2048.
//   8 warps: 4(M) x 2(N), each m32 x n64. 96 KB smem, 2 CTAs/SM, 128 regs.
//   B rows interleave a/gate halves of W => acc cols (2c,2c+1) = (a,gate).
//   3-slot / 2-in-flight cp.async ring, one sync/stage, 2-stage lookahead.
// ---------------------------------------------------------------------------
#define KST 64                       // k elements per stage (128 B/row)
#define STG_BYTES 16384              // 128 rows * 128 B
#define ST_A 0
#define ST_B (3 * STG_BYTES)
#define SMEM_TOTAL_G (6 * STG_BYTES) // 96 KB

__device__ __forceinline__ uint32_t sw128(uint32_t off) {
    return off ^ ((off >> 3) & 0x70);
}

__global__ __launch_bounds__(256, 2) void gemm_glu_f16(
    const float* __restrict__ bias, float* __restrict__ out, int m_base)
{
    extern __shared__ char smem[];
    const uint32_t sb = (uint32_t)__cvta_generic_to_shared(smem);
    const int tid  = threadIdx.x;
    const int lane = tid & 31;
    const int wid  = tid >> 5;
    const int warpM = wid & 3;
    const int warpN = wid >> 2;
    const int m0  = m_base + blockIdx.y * 128;
    const int nb0 = blockIdx.x * 64;

    auto load_stage = [&](int slot, int k0) {
#pragma unroll
        for (int i = 0; i < 8; i++) {
            int idx = tid + i * 256;
            int row = (idx >> 3) & 127, ch = idx & 7;
            uint32_t sw = sw128(row * 128 + ch * 16);
            if (idx < 1024) {
                cp_async16(smem + ST_A + slot * STG_BYTES + sw,
                           g_buf + (size_t)(m0 + row) * KDIM + k0 + ch * 8);
            } else {
                int q = row >> 1;
                int wrow = (row & 1) ? (NHALF + nb0 + q) : (nb0 + q);
                cp_async16(smem + ST_B + slot * STG_BYTES + sw,
                           w_h + (size_t)wrow * KDIM + k0 + ch * 8);
            }
        }
        cp_commit();
    };

    float acc[2][8][4];
#pragma unroll
    for (int mt = 0; mt < 2; mt++)
#pragma unroll
        for (int nt = 0; nt < 8; nt++)
#pragma unroll
            for (int c = 0; c < 4; c++) acc[mt][nt][c] = 0.f;

    const int NST = KDIM / KST;              // 32
    load_stage(0, 0);
    load_stage(1, KST);

    const uint32_t a_row = warpM * 32 + (lane & 15);
    const uint32_t a_kh8 = (lane >> 4) << 3;
    const uint32_t b_row = warpN * 64 + (lane & 7) + ((lane >> 4) << 3);
    const uint32_t b_kh8 = lane & 8;

    int slot = 0;
    for (int s = 0; s < NST; s++) {
        cp_wait<1>();
        __syncthreads();

        if (s + 2 < NST) {
            int ls = slot + 2; if (ls >= 3) ls -= 3;
            load_stage(ls, (s + 2) * KST);
        }

        const uint32_t abase = sb + ST_A + slot * STG_BYTES;
        const uint32_t bbase = sb + ST_B + slot * STG_BYTES;

#pragma unroll
        for (int k16 = 0; k16 < 4; k16++) {
            const uint32_t kk = k16 * 16;
            uint32_t a[2][4], bf[8][2];
#pragma unroll
            for (int mt = 0; mt < 2; mt++)
                ldsm_x4(a[mt][0], a[mt][1], a[mt][2], a[mt][3],
                        abase + sw128((a_row + mt * 16) * 128 + (kk + a_kh8) * 2));
#pragma unroll
            for (int nt2 = 0; nt2 < 4; nt2++)
                ldsm_x4(bf[2 * nt2][0], bf[2 * nt2][1], bf[2 * nt2 + 1][0], bf[2 * nt2 + 1][1],
                        bbase + sw128((b_row + nt2 * 16) * 128 + (kk + b_kh8) * 2));
#pragma unroll
            for (int mt = 0; mt < 2; mt++)
#pragma unroll
                for (int nt = 0; nt < 8; nt++)
                    mma_f16(acc[mt][nt], a[mt], bf[nt]);
        }

        if (++slot >= 3) slot = 0;
    }

#pragma unroll
    for (int mt = 0; mt < 2; mt++) {
        int row = m0 + warpM * 32 + mt * 16 + (lane >> 2);
#pragma unroll
        for (int nt = 0; nt < 8; nt++) {
            int col = nb0 + warpN * 32 + nt * 4 + (lane & 3);
            float ba = __ldg(bias + col);
            float bg = __ldg(bias + NHALF + col);

            float za0 = acc[mt][nt][0] + ba;
            float zg0 = acc[mt][nt][1] + bg;
            out[(size_t)row * NHALF + col] = za0 * (1.f / (1.f + __expf(-zg0)));

            float za1 = acc[mt][nt][2] + ba;
            float zg1 = acc[mt][nt][3] + bg;
            out[(size_t)(row + 8) * NHALF + col] = za1 * (1.f / (1.f + __expf(-zg1)));
        }
    }
}

// ---------------------------------------------------------------------------
// Launch: 2 chunks (one per batch). conv (49KB, 4/SM) + gemm (96KB, 2/SM)
// can co-reside (145KB <= 228KB) -> cross-stream overlap of conv chunk c+1
// with gemm chunk c.
// ---------------------------------------------------------------------------
#define NCHUNK 2
#define MCHUNK ((BB * LL) / NCHUNK)   // 4096 rows = one batch

extern "C" void kernel_launch(void* const* d_in, const int* in_sizes, int n_in,
                              void* d_out, int out_size)
{
    const float* u    = (const float*)d_in[0];  // [2,4096,2048]
    const float* kern = (const float*)d_in[1];  // [1,2048,128]
    const float* D    = (const float*)d_in[2];  // [1,2048]
    const float* W    = (const float*)d_in[3];  // [4096,2048]
    const float* bias = (const float*)d_in[4];  // [4096]
    float* out = (float*)d_out;                 // [2,4096,2048]

    static cudaStream_t s_gemm = nullptr;
    static cudaEvent_t ev_conv[NCHUNK];
    static cudaEvent_t ev_done;
    if (s_gemm == nullptr) {
        cudaStreamCreateWithFlags(&s_gemm, cudaStreamNonBlocking);
        for (int c = 0; c < NCHUNK; c++)
            cudaEventCreateWithFlags(&ev_conv[c], cudaEventDisableTiming);
        cudaEventCreateWithFlags(&ev_done, cudaEventDisableTiming);
        cudaFuncSetAttribute(gemm_glu_f16, cudaFuncAttributeMaxDynamicSharedMemorySize,
                             SMEM_TOTAL_G);
        cudaFuncSetAttribute(conv_gelu_f32x2, cudaFuncAttributeMaxDynamicSharedMemorySize,
                             CONV_SMEM);
    }

    wconv_kernel<<<8192, 256>>>(W);

    for (int c = 0; c < NCHUNK; c++) {
        conv_gelu_f32x2<<<dim3(LL / 128, HH / 32), 128, CONV_SMEM>>>(u, kern, D, c);
        cudaEventRecord(ev_conv[c], 0);
    }

    for (int c = 0; c < NCHUNK; c++) {
        cudaStreamWaitEvent(s_gemm, ev_conv[c], 0);
        gemm_glu_f16<<<dim3(NHALF / 64, MCHUNK / 128), 256, SMEM_TOTAL_G, s_gemm>>>(
            bias, out, c * MCHUNK);
    }

    cudaEventRecord(ev_done, s_gemm);
    cudaStreamWaitEvent(0, ev_done, 0);
}